// round 1
// baseline (speedup 1.0000x reference)
#include <cuda_runtime.h>
#include <math.h>

#define N_NODES 50000
#define N_EDGES 625000
#define N_GRAPHS 256
#define CH 128
#define N_OUT 10

// ---------------- scratch (no allocations allowed) ----------------
__device__ float g_z [N_NODES * CH];
__device__ float g_t1[N_NODES * CH];
__device__ float g_t2[N_NODES * CH];
__device__ float g_h [N_NODES * CH];

__device__ int   g_deg   [N_NODES];
__device__ int   g_cursor[N_NODES];
__device__ int   g_rowptr[N_NODES + 1];
__device__ int   g_csrsrc[N_EDGES];

__device__ float g_pooled[N_GRAPHS * CH];
__device__ float g_counts[N_GRAPHS];

// ---------------- small utility kernels ----------------
__global__ void zero_i32(int* p, int n) {
    int i = blockIdx.x * blockDim.x + threadIdx.x;
    if (i < n) p[i] = 0;
}
__global__ void zero_f32(float* p, int n) {
    int i = blockIdx.x * blockDim.x + threadIdx.x;
    if (i < n) p[i] = 0.0f;
}

// ---------------- CSR build ----------------
__global__ void count_deg(const int* __restrict__ dst, int* __restrict__ deg) {
    int e = blockIdx.x * blockDim.x + threadIdx.x;
    if (e < N_EDGES) atomicAdd(&deg[dst[e]], 1);
}

// single-block exclusive scan over N_NODES degrees
__global__ void scan_deg(const int* __restrict__ deg, int* __restrict__ rowptr) {
    __shared__ int part[1024];
    const int n = N_NODES;
    const int chunk = (n + 1023) / 1024;  // 49
    int t = threadIdx.x;
    int start = t * chunk;
    int s = 0;
    for (int i = 0; i < chunk; i++) {
        int idx = start + i;
        if (idx < n) s += deg[idx];
    }
    part[t] = s;
    __syncthreads();
    // Hillis-Steele inclusive scan
    for (int off = 1; off < 1024; off <<= 1) {
        int add = (t >= off) ? part[t - off] : 0;
        __syncthreads();
        part[t] += add;
        __syncthreads();
    }
    int run = (t == 0) ? 0 : part[t - 1];
    for (int i = 0; i < chunk; i++) {
        int idx = start + i;
        if (idx < n) { rowptr[idx] = run; run += deg[idx]; }
    }
    if (t == 1023) rowptr[n] = run;
}

__global__ void scatter_edges(const int* __restrict__ src, const int* __restrict__ dst,
                              const int* __restrict__ rowptr, int* __restrict__ cursor,
                              int* __restrict__ csrsrc) {
    int e = blockIdx.x * blockDim.x + threadIdx.x;
    if (e >= N_EDGES) return;
    int d = dst[e];
    int slot = rowptr[d] + atomicAdd(&cursor[d], 1);
    csrsrc[slot] = src[e];
}

// ---------------- aggregation: z[v] = h[v] + sum_{(u->v)} h[u] ----------------
// one warp per node, lane handles a float4 (32 lanes * 4 = 128 ch)
__global__ void agg_kernel(const float* __restrict__ h, float* __restrict__ z,
                           const int* __restrict__ rowptr, const int* __restrict__ csrsrc) {
    int warp = (blockIdx.x * blockDim.x + threadIdx.x) >> 5;
    int lane = threadIdx.x & 31;
    if (warp >= N_NODES) return;
    const float4* hv = (const float4*)h;
    float4 acc = hv[warp * 32 + lane];
    int beg = rowptr[warp], end = rowptr[warp + 1];
    for (int i = beg; i < end; i++) {
        int s = csrsrc[i];
        float4 v = hv[s * 32 + lane];
        acc.x += v.x; acc.y += v.y; acc.z += v.z; acc.w += v.w;
    }
    ((float4*)z)[warp * 32 + lane] = acc;
}

// ---------------- GEMM: C[M,128] = A[M,128] @ W[128,128] + bias (opt relu) ----
// block tile 64x128, BK=32, 256 threads, 4x8 micro-tile per thread
__global__ __launch_bounds__(256) void gemm_bias_act(
    const float* __restrict__ A, const float* __restrict__ W,
    const float* __restrict__ bias, float* __restrict__ C,
    int M, int relu)
{
    __shared__ __align__(16) float As[32][65];   // [k][m], +1 pad -> conflict-free
    __shared__ __align__(16) float Ws[32][128];  // [k][n]

    int tid = threadIdx.x;
    int tx = tid & 15;       // col group: cols tx*8 .. tx*8+7
    int ty = tid >> 4;       // row group: rows ty*4 .. ty*4+3
    int row0 = blockIdx.x * 64;

    float acc[4][8];
#pragma unroll
    for (int i = 0; i < 4; i++)
#pragma unroll
        for (int j = 0; j < 8; j++) acc[i][j] = 0.0f;

    for (int k0 = 0; k0 < 128; k0 += 32) {
        // load A tile transposed: 64 rows x 32 k -> As[k][m]
        // scalar loads, coalesced in global, conflict-free in smem (pad 65)
        for (int q = tid; q < 64 * 32; q += 256) {
            int r  = q >> 5;   // 0..63
            int kc = q & 31;   // 0..31
            int grow = row0 + r;
            float v = 0.0f;
            if (grow < M) v = A[grow * 128 + k0 + kc];
            As[kc][r] = v;
        }
        // load W tile: 32 k x 128 n, float4
        for (int q = tid; q < (32 * 128) / 4; q += 256) {
            int kk = q >> 5;  // 0..31
            int c4 = q & 31;  // 0..31
            *(float4*)&Ws[kk][c4 * 4] = *(const float4*)(W + (k0 + kk) * 128 + c4 * 4);
        }
        __syncthreads();

#pragma unroll
        for (int kk = 0; kk < 32; kk++) {
            float av[4];
#pragma unroll
            for (int i = 0; i < 4; i++) av[i] = As[kk][ty * 4 + i];
            float4 b0 = *(const float4*)&Ws[kk][tx * 8];
            float4 b1 = *(const float4*)&Ws[kk][tx * 8 + 4];
            float bv[8] = {b0.x, b0.y, b0.z, b0.w, b1.x, b1.y, b1.z, b1.w};
#pragma unroll
            for (int i = 0; i < 4; i++)
#pragma unroll
                for (int j = 0; j < 8; j++) acc[i][j] += av[i] * bv[j];
        }
        __syncthreads();
    }

#pragma unroll
    for (int i = 0; i < 4; i++) {
        int r = row0 + ty * 4 + i;
        if (r < M) {
#pragma unroll
            for (int j = 0; j < 8; j++) {
                float v = acc[i][j] + bias[tx * 8 + j];
                if (relu) v = fmaxf(v, 0.0f);
                C[r * 128 + tx * 8 + j] = v;
            }
        }
    }
}

// ---------------- pooling scatter (segment sum over graphs) ----------------
__global__ void pool_kernel(const float* __restrict__ h, const int* __restrict__ gid,
                            float* __restrict__ pooled, float* __restrict__ counts) {
    int warp = (blockIdx.x * blockDim.x + threadIdx.x) >> 5;
    int lane = threadIdx.x & 31;
    if (warp >= N_NODES) return;
    int g = gid[warp];
    float4 v = ((const float4*)h)[warp * 32 + lane];
    float* base = pooled + g * 128 + lane * 4;
    atomicAdd(base + 0, v.x);
    atomicAdd(base + 1, v.y);
    atomicAdd(base + 2, v.z);
    atomicAdd(base + 3, v.w);
    if (lane == 0) atomicAdd(&counts[g], 1.0f);
}

// ---------------- head: mean -> dense(relu) -> dense -> softmax -------------
__global__ void head_kernel(const float* __restrict__ pooled, const float* __restrict__ counts,
                            const float* __restrict__ W1, const float* __restrict__ b1,
                            const float* __restrict__ W2, const float* __restrict__ b2,
                            float* __restrict__ out) {
    int g = blockIdx.x;
    int t = threadIdx.x;  // 128 threads
    __shared__ float p[128];
    __shared__ float h1[128];
    __shared__ float logits[N_OUT];

    float cnt = fmaxf(counts[g], 1.0f);
    p[t] = pooled[g * 128 + t] / cnt;
    __syncthreads();

    float acc = b1[t];
#pragma unroll 8
    for (int k = 0; k < 128; k++) acc += p[k] * W1[k * 128 + t];
    h1[t] = fmaxf(acc, 0.0f);
    __syncthreads();

    if (t < N_OUT) {
        float a = b2[t];
#pragma unroll 8
        for (int k = 0; k < 128; k++) a += h1[k] * W2[k * N_OUT + t];
        logits[t] = a;
    }
    __syncthreads();

    if (t == 0) {
        float m = -1e30f;
#pragma unroll
        for (int o = 0; o < N_OUT; o++) m = fmaxf(m, logits[o]);
        float e[N_OUT], s = 0.0f;
#pragma unroll
        for (int o = 0; o < N_OUT; o++) { e[o] = __expf(logits[o] - m); s += e[o]; }
        float inv = 1.0f / s;
#pragma unroll
        for (int o = 0; o < N_OUT; o++) out[g * N_OUT + o] = e[o] * inv;
    }
}

// ---------------- launch ----------------
extern "C" void kernel_launch(void* const* d_in, const int* in_sizes, int n_in,
                              void* d_out, int out_size) {
    const float* x        = (const float*)d_in[0];
    const int*   edge_src = (const int*)  d_in[1];
    const int*   edge_dst = (const int*)  d_in[2];
    const int*   graph_id = (const int*)  d_in[3];
    const float* conv_W   = (const float*)d_in[4];  // (3,3,128,128)
    const float* conv_b   = (const float*)d_in[5];  // (3,3,128)
    const float* d1_W     = (const float*)d_in[6];
    const float* d1_b     = (const float*)d_in[7];
    const float* d2_W     = (const float*)d_in[8];
    const float* d2_b     = (const float*)d_in[9];
    float* out = (float*)d_out;

    float *z, *t1, *t2, *h, *pooled, *counts;
    int *deg, *cursor, *rowptr, *csrsrc;
    cudaGetSymbolAddress((void**)&z,      g_z);
    cudaGetSymbolAddress((void**)&t1,     g_t1);
    cudaGetSymbolAddress((void**)&t2,     g_t2);
    cudaGetSymbolAddress((void**)&h,      g_h);
    cudaGetSymbolAddress((void**)&pooled, g_pooled);
    cudaGetSymbolAddress((void**)&counts, g_counts);
    cudaGetSymbolAddress((void**)&deg,    g_deg);
    cudaGetSymbolAddress((void**)&cursor, g_cursor);
    cudaGetSymbolAddress((void**)&rowptr, g_rowptr);
    cudaGetSymbolAddress((void**)&csrsrc, g_csrsrc);

    const int TB = 256;
    // ---- CSR build (per launch, deterministic work) ----
    zero_i32<<<(2 * N_NODES + TB - 1) / TB, TB>>>(deg, N_NODES);        // deg
    zero_i32<<<(N_NODES + TB - 1) / TB, TB>>>(cursor, N_NODES);         // cursor
    count_deg<<<(N_EDGES + TB - 1) / TB, TB>>>(edge_dst, deg);
    scan_deg<<<1, 1024>>>(deg, rowptr);
    scatter_edges<<<(N_EDGES + TB - 1) / TB, TB>>>(edge_src, edge_dst, rowptr, cursor, csrsrc);

    const int aggBlocks  = (N_NODES * 32 + TB - 1) / TB;  // one warp per node
    const int gemmBlocks = (N_NODES + 63) / 64;

    const float* hin = x;
    for (int l = 0; l < 3; l++) {
        const float* W0 = conv_W + (size_t)(l * 3 + 0) * CH * CH;
        const float* W1p = conv_W + (size_t)(l * 3 + 1) * CH * CH;
        const float* W2p = conv_W + (size_t)(l * 3 + 2) * CH * CH;
        const float* b0 = conv_b + (size_t)(l * 3 + 0) * CH;
        const float* b1p = conv_b + (size_t)(l * 3 + 1) * CH;
        const float* b2p = conv_b + (size_t)(l * 3 + 2) * CH;

        agg_kernel<<<aggBlocks, TB>>>(hin, z, rowptr, csrsrc);
        gemm_bias_act<<<gemmBlocks, 256>>>(z,  W0,  b0,  t1, N_NODES, 1);
        gemm_bias_act<<<gemmBlocks, 256>>>(t1, W1p, b1p, t2, N_NODES, 1);
        gemm_bias_act<<<gemmBlocks, 256>>>(t2, W2p, b2p, h,  N_NODES, 0);
        hin = h;
    }

    // ---- pooling + head ----
    zero_f32<<<(N_GRAPHS * CH + TB - 1) / TB, TB>>>(pooled, N_GRAPHS * CH);
    zero_f32<<<1, N_GRAPHS>>>(counts, N_GRAPHS);
    pool_kernel<<<aggBlocks, TB>>>(h, graph_id, pooled, counts);
    head_kernel<<<N_GRAPHS, 128>>>(pooled, counts, d1_W, d1_b, d2_W, d2_b, out);
}

// round 2
// speedup vs baseline: 2.0423x; 2.0423x over previous
#include <cuda_runtime.h>
#include <math.h>

#define N_NODES 50000
#define N_EDGES 625000
#define N_GRAPHS 256
#define CH 128
#define N_OUT 10

// ---------------- scratch (no allocations allowed) ----------------
__device__ float g_z [N_NODES * CH];
__device__ float g_t1[N_NODES * CH];
__device__ float g_t2[N_NODES * CH];
__device__ float g_h [N_NODES * CH];

__device__ int   g_deg   [N_NODES];
__device__ int   g_cursor[N_NODES];
__device__ int   g_rowptr[N_NODES + 1];
__device__ int   g_csrsrc[N_EDGES];
__device__ int   g_bsums [64];
__device__ int   g_boff  [64];

__device__ float g_pooled[N_GRAPHS * CH];
__device__ float g_counts[N_GRAPHS];

// ---------------- utility ----------------
__global__ void zero_deg_cursor(int* deg, int* cursor) {
    int i = blockIdx.x * blockDim.x + threadIdx.x;
    if (i < N_NODES) { deg[i] = 0; cursor[i] = 0; }
}
__global__ void zero_pool(float* pooled, float* counts) {
    int i = blockIdx.x * blockDim.x + threadIdx.x;
    if (i < N_GRAPHS * CH) pooled[i] = 0.0f;
    if (i < N_GRAPHS) counts[i] = 0.0f;
}

// ---------------- CSR build ----------------
__global__ void count_deg(const int* __restrict__ dst, int* __restrict__ deg) {
    int e = blockIdx.x * blockDim.x + threadIdx.x;
    if (e < N_EDGES) atomicAdd(&deg[dst[e]], 1);
}

// multi-block scan, stage 1: per-block exclusive scan + block sums
__global__ void scan_blocks(const int* __restrict__ deg, int* __restrict__ rowptr,
                            int* __restrict__ bsums) {
    __shared__ int wsum[32];
    int gid = blockIdx.x * 1024 + threadIdx.x;
    int v = (gid < N_NODES) ? deg[gid] : 0;
    int lane = threadIdx.x & 31, wid = threadIdx.x >> 5;
    int x = v;
#pragma unroll
    for (int o = 1; o < 32; o <<= 1) {
        int y = __shfl_up_sync(0xffffffffu, x, o);
        if (lane >= o) x += y;
    }
    if (lane == 31) wsum[wid] = x;
    __syncthreads();
    if (wid == 0) {
        int s = wsum[lane];
#pragma unroll
        for (int o = 1; o < 32; o <<= 1) {
            int y = __shfl_up_sync(0xffffffffu, s, o);
            if (lane >= o) s += y;
        }
        wsum[lane] = s;
    }
    __syncthreads();
    int base = (wid > 0) ? wsum[wid - 1] : 0;
    int incl = base + x;
    if (gid < N_NODES) rowptr[gid] = incl - v;  // block-local exclusive
    if (threadIdx.x == 1023) bsums[blockIdx.x] = incl;
}

// stage 2: scan 49 block sums (smem-cached, thread 0 serial over smem)
__global__ void scan_bsums(const int* __restrict__ bsums, int* __restrict__ boff,
                           int* __restrict__ rowptr, int nblocks) {
    __shared__ int s[64];
    int t = threadIdx.x;
    s[t] = (t < nblocks) ? bsums[t] : 0;
    __syncthreads();
    if (t == 0) {
        int run = 0;
        for (int i = 0; i < nblocks; i++) { int v = s[i]; boff[i] = run; run += v; }
        rowptr[N_NODES] = run;
    }
}

// stage 3: add block offsets
__global__ void add_boff(int* __restrict__ rowptr, const int* __restrict__ boff) {
    int gid = blockIdx.x * 1024 + threadIdx.x;
    if (gid < N_NODES) rowptr[gid] += boff[blockIdx.x];
}

__global__ void scatter_edges(const int* __restrict__ src, const int* __restrict__ dst,
                              const int* __restrict__ rowptr, int* __restrict__ cursor,
                              int* __restrict__ csrsrc) {
    int e = blockIdx.x * blockDim.x + threadIdx.x;
    if (e >= N_EDGES) return;
    int d = dst[e];
    int slot = rowptr[d] + atomicAdd(&cursor[d], 1);
    csrsrc[slot] = src[e];
}

// ---------------- aggregation: z[v] = h[v] + sum_{(u->v)} h[u] ----------------
__global__ void agg_kernel(const float* __restrict__ h, float* __restrict__ z,
                           const int* __restrict__ rowptr, const int* __restrict__ csrsrc) {
    int warp = (blockIdx.x * blockDim.x + threadIdx.x) >> 5;
    int lane = threadIdx.x & 31;
    if (warp >= N_NODES) return;
    const float4* hv = (const float4*)h;
    float4 acc = hv[warp * 32 + lane];
    int beg = rowptr[warp], end = rowptr[warp + 1];
    for (int i = beg; i < end; i++) {
        int s = csrsrc[i];
        float4 v = hv[s * 32 + lane];
        acc.x += v.x; acc.y += v.y; acc.z += v.z; acc.w += v.w;
    }
    ((float4*)z)[warp * 32 + lane] = acc;
}

// ---------------- tf32 tensor-core GEMM ----------------
// C[M,128] = A[M,128] @ W[128,128] + bias (opt relu)
// block tile 64(M) x 128(N) x 128(K, full), 256 threads = 8 warps
// warp w: rows (w&3)*16, cols (w>>2)*64; mma m16n8k8 tf32, fp32 accum
#define AS_STRIDE 132   // 132 % 32 == 4 -> A-frag bank = (4r+c)%32, bijective
#define WS_STRIDE 136   // 136 % 32 == 8 -> B-frag bank = (8k+n)%32, bijective
#define GEMM_SMEM ((64 * AS_STRIDE + 128 * WS_STRIDE) * 4)

__device__ __forceinline__ float to_tf32(float x) {
    float y;
    asm("cvt.rna.tf32.f32 %0, %1;" : "=f"(y) : "f"(x));
    return y;
}

__device__ __forceinline__ void mma_tf32(float* d, float a0, float a1, float a2, float a3,
                                         float b0, float b1) {
    asm volatile(
        "mma.sync.aligned.m16n8k8.row.col.f32.tf32.tf32.f32 "
        "{%0,%1,%2,%3}, {%4,%5,%6,%7}, {%8,%9}, {%0,%1,%2,%3};"
        : "+f"(d[0]), "+f"(d[1]), "+f"(d[2]), "+f"(d[3])
        : "r"(__float_as_uint(a0)), "r"(__float_as_uint(a1)),
          "r"(__float_as_uint(a2)), "r"(__float_as_uint(a3)),
          "r"(__float_as_uint(b0)), "r"(__float_as_uint(b1)));
}

__global__ __launch_bounds__(256, 2) void gemm_tc(
    const float* __restrict__ A, const float* __restrict__ W,
    const float* __restrict__ bias, float* __restrict__ C,
    int M, int relu)
{
    extern __shared__ __align__(16) float smem[];
    float* As = smem;                    // [64][AS_STRIDE]
    float* Ws = smem + 64 * AS_STRIDE;   // [128][WS_STRIDE]

    int tid = threadIdx.x;
    int row0 = blockIdx.x * 64;

    // load A tile (64 x 128) as tf32, float4 global loads
    for (int q = tid; q < 64 * 32; q += 256) {
        int r = q >> 5, c4 = q & 31;
        int grow = row0 + r;
        float4 v = make_float4(0.f, 0.f, 0.f, 0.f);
        if (grow < M) v = *(const float4*)(A + grow * 128 + c4 * 4);
        float* d = As + r * AS_STRIDE + c4 * 4;
        d[0] = to_tf32(v.x); d[1] = to_tf32(v.y); d[2] = to_tf32(v.z); d[3] = to_tf32(v.w);
    }
    // load W (128 x 128) as tf32
    for (int q = tid; q < 128 * 32; q += 256) {
        int k = q >> 5, c4 = q & 31;
        float4 v = *(const float4*)(W + k * 128 + c4 * 4);
        float* d = Ws + k * WS_STRIDE + c4 * 4;
        d[0] = to_tf32(v.x); d[1] = to_tf32(v.y); d[2] = to_tf32(v.z); d[3] = to_tf32(v.w);
    }
    __syncthreads();

    int lane = tid & 31, w = tid >> 5;
    int wm = w & 3, wn = w >> 2;
    int grp = lane >> 2, tig = lane & 3;  // groupID, thread-in-group

    float acc[8][4];
#pragma unroll
    for (int j = 0; j < 8; j++)
#pragma unroll
        for (int i = 0; i < 4; i++) acc[j][i] = 0.0f;

    const float* Abase = As + (wm * 16 + grp) * AS_STRIDE + tig;
    const float* Bbase = Ws + tig * WS_STRIDE + wn * 64 + grp;

#pragma unroll
    for (int ks = 0; ks < 16; ks++) {
        float a0 = Abase[ks * 8];
        float a1 = Abase[8 * AS_STRIDE + ks * 8];
        float a2 = Abase[ks * 8 + 4];
        float a3 = Abase[8 * AS_STRIDE + ks * 8 + 4];
#pragma unroll
        for (int j = 0; j < 8; j++) {
            float b0 = Bbase[(ks * 8) * WS_STRIDE + j * 8];
            float b1 = Bbase[(ks * 8 + 4) * WS_STRIDE + j * 8];
            mma_tf32(acc[j], a0, a1, a2, a3, b0, b1);
        }
    }

    // epilogue: d0,d1 -> (row, col..col+1); d2,d3 -> (row+8, ...)
    int rA = row0 + wm * 16 + grp;
    int col0 = wn * 64 + tig * 2;
#pragma unroll
    for (int j = 0; j < 8; j++) {
        int c = col0 + j * 8;
        float bx = bias[c], by = bias[c + 1];
        if (rA < M) {
            float v0 = acc[j][0] + bx, v1 = acc[j][1] + by;
            if (relu) { v0 = fmaxf(v0, 0.f); v1 = fmaxf(v1, 0.f); }
            *(float2*)(C + rA * 128 + c) = make_float2(v0, v1);
        }
        if (rA + 8 < M) {
            float v2 = acc[j][2] + bx, v3 = acc[j][3] + by;
            if (relu) { v2 = fmaxf(v2, 0.f); v3 = fmaxf(v3, 0.f); }
            *(float2*)(C + (rA + 8) * 128 + c) = make_float2(v2, v3);
        }
    }
}

// ---------------- pooling scatter ----------------
__global__ void pool_kernel(const float* __restrict__ h, const int* __restrict__ gid,
                            float* __restrict__ pooled, float* __restrict__ counts) {
    int warp = (blockIdx.x * blockDim.x + threadIdx.x) >> 5;
    int lane = threadIdx.x & 31;
    if (warp >= N_NODES) return;
    int g = gid[warp];
    float4 v = ((const float4*)h)[warp * 32 + lane];
    float* base = pooled + g * 128 + lane * 4;
    atomicAdd(base + 0, v.x);
    atomicAdd(base + 1, v.y);
    atomicAdd(base + 2, v.z);
    atomicAdd(base + 3, v.w);
    if (lane == 0) atomicAdd(&counts[g], 1.0f);
}

// ---------------- head ----------------
__global__ void head_kernel(const float* __restrict__ pooled, const float* __restrict__ counts,
                            const float* __restrict__ W1, const float* __restrict__ b1,
                            const float* __restrict__ W2, const float* __restrict__ b2,
                            float* __restrict__ out) {
    int g = blockIdx.x;
    int t = threadIdx.x;
    __shared__ float p[128];
    __shared__ float h1[128];
    __shared__ float logits[N_OUT];

    float cnt = fmaxf(counts[g], 1.0f);
    p[t] = pooled[g * 128 + t] / cnt;
    __syncthreads();

    float acc = b1[t];
#pragma unroll 8
    for (int k = 0; k < 128; k++) acc += p[k] * W1[k * 128 + t];
    h1[t] = fmaxf(acc, 0.0f);
    __syncthreads();

    if (t < N_OUT) {
        float a = b2[t];
#pragma unroll 8
        for (int k = 0; k < 128; k++) a += h1[k] * W2[k * N_OUT + t];
        logits[t] = a;
    }
    __syncthreads();

    if (t == 0) {
        float m = -1e30f;
#pragma unroll
        for (int o = 0; o < N_OUT; o++) m = fmaxf(m, logits[o]);
        float e[N_OUT], s = 0.0f;
#pragma unroll
        for (int o = 0; o < N_OUT; o++) { e[o] = __expf(logits[o] - m); s += e[o]; }
        float inv = 1.0f / s;
#pragma unroll
        for (int o = 0; o < N_OUT; o++) out[g * N_OUT + o] = e[o] * inv;
    }
}

// ---------------- launch ----------------
extern "C" void kernel_launch(void* const* d_in, const int* in_sizes, int n_in,
                              void* d_out, int out_size) {
    const float* x        = (const float*)d_in[0];
    const int*   edge_src = (const int*)  d_in[1];
    const int*   edge_dst = (const int*)  d_in[2];
    const int*   graph_id = (const int*)  d_in[3];
    const float* conv_W   = (const float*)d_in[4];
    const float* conv_b   = (const float*)d_in[5];
    const float* d1_W     = (const float*)d_in[6];
    const float* d1_b     = (const float*)d_in[7];
    const float* d2_W     = (const float*)d_in[8];
    const float* d2_b     = (const float*)d_in[9];
    float* out = (float*)d_out;

    float *z, *t1, *t2, *h, *pooled, *counts;
    int *deg, *cursor, *rowptr, *csrsrc, *bsums, *boff;
    cudaGetSymbolAddress((void**)&z,      g_z);
    cudaGetSymbolAddress((void**)&t1,     g_t1);
    cudaGetSymbolAddress((void**)&t2,     g_t2);
    cudaGetSymbolAddress((void**)&h,      g_h);
    cudaGetSymbolAddress((void**)&pooled, g_pooled);
    cudaGetSymbolAddress((void**)&counts, g_counts);
    cudaGetSymbolAddress((void**)&deg,    g_deg);
    cudaGetSymbolAddress((void**)&cursor, g_cursor);
    cudaGetSymbolAddress((void**)&rowptr, g_rowptr);
    cudaGetSymbolAddress((void**)&csrsrc, g_csrsrc);
    cudaGetSymbolAddress((void**)&bsums,  g_bsums);
    cudaGetSymbolAddress((void**)&boff,   g_boff);

    cudaFuncSetAttribute(gemm_tc, cudaFuncAttributeMaxDynamicSharedMemorySize, GEMM_SMEM);

    const int TB = 256;
    const int scanBlocks = (N_NODES + 1023) / 1024;  // 49

    // ---- CSR build ----
    zero_deg_cursor<<<(N_NODES + TB - 1) / TB, TB>>>(deg, cursor);
    count_deg<<<(N_EDGES + TB - 1) / TB, TB>>>(edge_dst, deg);
    scan_blocks<<<scanBlocks, 1024>>>(deg, rowptr, bsums);
    scan_bsums<<<1, 64>>>(bsums, boff, rowptr, scanBlocks);
    add_boff<<<scanBlocks, 1024>>>(rowptr, boff);
    scatter_edges<<<(N_EDGES + TB - 1) / TB, TB>>>(edge_src, edge_dst, rowptr, cursor, csrsrc);

    const int aggBlocks  = (N_NODES * 32 + TB - 1) / TB;
    const int gemmBlocks = (N_NODES + 63) / 64;

    const float* hin = x;
    for (int l = 0; l < 3; l++) {
        const float* W0  = conv_W + (size_t)(l * 3 + 0) * CH * CH;
        const float* W1p = conv_W + (size_t)(l * 3 + 1) * CH * CH;
        const float* W2p = conv_W + (size_t)(l * 3 + 2) * CH * CH;
        const float* b0  = conv_b + (size_t)(l * 3 + 0) * CH;
        const float* b1p = conv_b + (size_t)(l * 3 + 1) * CH;
        const float* b2p = conv_b + (size_t)(l * 3 + 2) * CH;

        agg_kernel<<<aggBlocks, TB>>>(hin, z, rowptr, csrsrc);
        gemm_tc<<<gemmBlocks, 256, GEMM_SMEM>>>(z,  W0,  b0,  t1, N_NODES, 1);
        gemm_tc<<<gemmBlocks, 256, GEMM_SMEM>>>(t1, W1p, b1p, t2, N_NODES, 1);
        gemm_tc<<<gemmBlocks, 256, GEMM_SMEM>>>(t2, W2p, b2p, h,  N_NODES, 0);
        hin = h;
    }

    zero_pool<<<(N_GRAPHS * CH + TB - 1) / TB, TB>>>(pooled, counts);
    pool_kernel<<<aggBlocks, TB>>>(h, graph_id, pooled, counts);
    head_kernel<<<N_GRAPHS, 128>>>(pooled, counts, d1_W, d1_b, d2_W, d2_b, out);
}

// round 4
// speedup vs baseline: 3.5231x; 1.7251x over previous
#include <cuda_runtime.h>
#include <cuda_fp16.h>
#include <cstdint>
#include <math.h>

#define N_NODES 50000
#define N_EDGES 625000
#define N_GRAPHS 256
#define CH 128
#define N_OUT 10

// ---------------- scratch (no allocations allowed) ----------------
__device__ float  g_z [N_NODES * CH];
__device__ float  g_t1[N_NODES * CH];
__device__ float  g_t2[N_NODES * CH];
__device__ float  g_h [N_NODES * CH];
__device__ __half g_Wh[9 * CH * CH];   // fp16, transposed [n][k]

__device__ int   g_deg   [N_NODES];
__device__ int   g_cursor[N_NODES];
__device__ int   g_rowptr[N_NODES + 1];
__device__ int   g_csrsrc[N_EDGES];
__device__ int   g_bsums [64];

__device__ float g_pooled[N_GRAPHS * CH];
__device__ float g_counts[N_GRAPHS];

// ---------------- utility ----------------
__global__ void zero_deg_cursor(int* deg, int* cursor) {
    int i = blockIdx.x * blockDim.x + threadIdx.x;
    if (i < N_NODES) { deg[i] = 0; cursor[i] = 0; }
}
__global__ void zero_pool(float* pooled, float* counts) {
    int i = blockIdx.x * blockDim.x + threadIdx.x;
    if (i < N_GRAPHS * CH) pooled[i] = 0.0f;
    if (i < N_GRAPHS) counts[i] = 0.0f;
}

// ---------------- W transpose + fp16 convert (once per launch) -------------
__global__ void wh_prep(const float* __restrict__ W, __half* __restrict__ Wh) {
    __shared__ float tile[32][33];
    int g = blockIdx.z;
    int tx = threadIdx.x, ty = threadIdx.y;
    int kt = blockIdx.x * 32, nt = blockIdx.y * 32;
    const float* Wg = W + g * CH * CH;
    __half* Whg = Wh + g * CH * CH;
#pragma unroll
    for (int i = 0; i < 32; i += 8)
        tile[ty + i][tx] = Wg[(kt + ty + i) * CH + nt + tx];
    __syncthreads();
#pragma unroll
    for (int i = 0; i < 32; i += 8)
        Whg[(nt + ty + i) * CH + kt + tx] = __float2half_rn(tile[tx][ty + i]);
}

// ---------------- CSR build ----------------
__global__ void count_deg(const int* __restrict__ dst, int* __restrict__ deg) {
    int e = blockIdx.x * blockDim.x + threadIdx.x;
    if (e < N_EDGES) atomicAdd(&deg[dst[e]], 1);
}

__global__ void scan_blocks(const int* __restrict__ deg, int* __restrict__ rowptr,
                            int* __restrict__ bsums) {
    __shared__ int wsum[32];
    int gid = blockIdx.x * 1024 + threadIdx.x;
    int v = (gid < N_NODES) ? deg[gid] : 0;
    int lane = threadIdx.x & 31, wid = threadIdx.x >> 5;
    int x = v;
#pragma unroll
    for (int o = 1; o < 32; o <<= 1) {
        int y = __shfl_up_sync(0xffffffffu, x, o);
        if (lane >= o) x += y;
    }
    if (lane == 31) wsum[wid] = x;
    __syncthreads();
    if (wid == 0) {
        int s = wsum[lane];
#pragma unroll
        for (int o = 1; o < 32; o <<= 1) {
            int y = __shfl_up_sync(0xffffffffu, s, o);
            if (lane >= o) s += y;
        }
        wsum[lane] = s;
    }
    __syncthreads();
    int base = (wid > 0) ? wsum[wid - 1] : 0;
    int incl = base + x;
    if (gid < N_NODES) rowptr[gid] = incl - v;
    if (threadIdx.x == 1023) bsums[blockIdx.x] = incl;
}

__global__ void add_boff(int* __restrict__ rowptr, const int* __restrict__ bsums, int nblocks) {
    __shared__ int pre;
    if (threadIdx.x == 0) {
        int run = 0;
        for (int i = 0; i < (int)blockIdx.x; i++) run += bsums[i];
        pre = run;
        if ((int)blockIdx.x == nblocks - 1)
            rowptr[N_NODES] = run + bsums[nblocks - 1];
    }
    __syncthreads();
    int gid = blockIdx.x * 1024 + threadIdx.x;
    if (gid < N_NODES) rowptr[gid] += pre;
}

__global__ void scatter_edges(const int* __restrict__ src, const int* __restrict__ dst,
                              const int* __restrict__ rowptr, int* __restrict__ cursor,
                              int* __restrict__ csrsrc) {
    int e = blockIdx.x * blockDim.x + threadIdx.x;
    if (e >= N_EDGES) return;
    int d = dst[e];
    int slot = rowptr[d] + atomicAdd(&cursor[d], 1);
    csrsrc[slot] = src[e];
}

// ---------------- aggregation: z[v] = h[v] + sum_{(u->v)} h[u] ----------------
__global__ void agg_kernel(const float* __restrict__ h, float* __restrict__ z,
                           const int* __restrict__ rowptr, const int* __restrict__ csrsrc) {
    int warp = (blockIdx.x * blockDim.x + threadIdx.x) >> 5;
    int lane = threadIdx.x & 31;
    if (warp >= N_NODES) return;
    const float4* hv = (const float4*)h;
    float4 acc = hv[warp * 32 + lane];
    int beg = rowptr[warp], end = rowptr[warp + 1];
    for (int i = beg; i < end; i++) {
        int s = csrsrc[i];
        float4 v = hv[s * 32 + lane];
        acc.x += v.x; acc.y += v.y; acc.z += v.z; acc.w += v.w;
    }
    ((float4*)z)[warp * 32 + lane] = acc;
}

// ---------------- fp16 tensor-core GEMM (legacy mma.sync, fp32 accum) -------
// C[M,128] = A[M,128] @ Wh^T + bias (opt relu); Wh is [n][k] fp16.
// CTA tile 128(M) x 128(N), K=128 full. 8 warps: 4(M) x 2(N), warp = 32x64.
// smem halves, padded stride 136 -> all fragment LDS.32 conflict-free.
#define HS 136
#define GEMM_SMEM (2 * 128 * HS * 2)   // 69632 B

__device__ __forceinline__ void mma16816(float* d, uint32_t a0, uint32_t a1,
                                         uint32_t a2, uint32_t a3,
                                         uint32_t b0, uint32_t b1) {
    asm volatile(
        "mma.sync.aligned.m16n8k16.row.col.f32.f16.f16.f32 "
        "{%0,%1,%2,%3}, {%4,%5,%6,%7}, {%8,%9}, {%0,%1,%2,%3};"
        : "+f"(d[0]), "+f"(d[1]), "+f"(d[2]), "+f"(d[3])
        : "r"(a0), "r"(a1), "r"(a2), "r"(a3), "r"(b0), "r"(b1));
}

__global__ __launch_bounds__(256, 2) void gemm_fp16(
    const float* __restrict__ A, const __half* __restrict__ Wh,
    const float* __restrict__ bias, float* __restrict__ C,
    int M, int relu)
{
    extern __shared__ __align__(16) char smem[];
    __half* Ash = (__half*)smem;             // [128][HS]
    __half* Bsh = Ash + 128 * HS;            // [128][HS]

    int tid = threadIdx.x;
    int row0 = blockIdx.x * 128;

    // stage A (fp32 -> fp16) : 128 rows x 128 cols
#pragma unroll
    for (int it = 0; it < 16; it++) {
        int q = tid + it * 256;          // 0..4095
        int r = q >> 5;                  // row
        int k4 = q & 31;                 // float4 index
        float4 v = make_float4(0.f, 0.f, 0.f, 0.f);
        int gr = row0 + r;
        if (gr < M) v = *(const float4*)(A + (size_t)gr * 128 + k4 * 4);
        __half2 h0 = __floats2half2_rn(v.x, v.y);
        __half2 h1 = __floats2half2_rn(v.z, v.w);
        *(__half2*)(Ash + r * HS + k4 * 4)     = h0;
        *(__half2*)(Ash + r * HS + k4 * 4 + 2) = h1;
    }
    // stage B (already fp16, [n][k]) : 128 x 128 halves via 8-byte loads
#pragma unroll
    for (int it = 0; it < 16; it++) {
        int q = tid + it * 256;
        int n = q >> 5;
        int k4 = q & 31;
        uint2 w = *(const uint2*)(Wh + (size_t)n * 128 + k4 * 4);
        *(uint2*)(Bsh + n * HS + k4 * 4) = w;
    }
    __syncthreads();

    int lane = tid & 31, w = tid >> 5;
    int wm = w & 3, wn = w >> 2;           // 4 x 2 warp grid
    int m0 = wm * 32, n0 = wn * 64;
    int grp = lane >> 2, tig = lane & 3;

    float acc[2][8][4];
#pragma unroll
    for (int mt = 0; mt < 2; mt++)
#pragma unroll
        for (int j = 0; j < 8; j++)
#pragma unroll
            for (int i = 0; i < 4; i++) acc[mt][j][i] = 0.0f;

#pragma unroll
    for (int ks = 0; ks < 8; ks++) {
        uint32_t af[2][4];
#pragma unroll
        for (int mt = 0; mt < 2; mt++) {
            const __half* p = Ash + (m0 + mt * 16 + grp) * HS + ks * 16 + tig * 2;
            af[mt][0] = *(const uint32_t*)p;
            af[mt][1] = *(const uint32_t*)(p + 8 * HS);
            af[mt][2] = *(const uint32_t*)(p + 8);
            af[mt][3] = *(const uint32_t*)(p + 8 * HS + 8);
        }
#pragma unroll
        for (int j = 0; j < 8; j++) {
            const __half* q = Bsh + (n0 + j * 8 + grp) * HS + ks * 16 + tig * 2;
            uint32_t b0 = *(const uint32_t*)q;
            uint32_t b1 = *(const uint32_t*)(q + 8);
            mma16816(acc[0][j], af[0][0], af[0][1], af[0][2], af[0][3], b0, b1);
            mma16816(acc[1][j], af[1][0], af[1][1], af[1][2], af[1][3], b0, b1);
        }
    }

    // epilogue: c0,c1 -> (row, col..col+1); c2,c3 -> (row+8, ...)
#pragma unroll
    for (int mt = 0; mt < 2; mt++) {
        int r = row0 + m0 + mt * 16 + grp;
#pragma unroll
        for (int j = 0; j < 8; j++) {
            int c = n0 + j * 8 + tig * 2;
            float bx = __ldg(bias + c), by = __ldg(bias + c + 1);
            if (r < M) {
                float v0 = acc[mt][j][0] + bx, v1 = acc[mt][j][1] + by;
                if (relu) { v0 = fmaxf(v0, 0.f); v1 = fmaxf(v1, 0.f); }
                *(float2*)(C + (size_t)r * 128 + c) = make_float2(v0, v1);
            }
            if (r + 8 < M) {
                float v2 = acc[mt][j][2] + bx, v3 = acc[mt][j][3] + by;
                if (relu) { v2 = fmaxf(v2, 0.f); v3 = fmaxf(v3, 0.f); }
                *(float2*)(C + (size_t)(r + 8) * 128 + c) = make_float2(v2, v3);
            }
        }
    }
}

// ---------------- pooling scatter ----------------
__global__ void pool_kernel(const float* __restrict__ h, const int* __restrict__ gid,
                            float* __restrict__ pooled, float* __restrict__ counts) {
    int warp = (blockIdx.x * blockDim.x + threadIdx.x) >> 5;
    int lane = threadIdx.x & 31;
    if (warp >= N_NODES) return;
    int g = gid[warp];
    float4 v = ((const float4*)h)[warp * 32 + lane];
    float* base = pooled + g * 128 + lane * 4;
    atomicAdd(base + 0, v.x);
    atomicAdd(base + 1, v.y);
    atomicAdd(base + 2, v.z);
    atomicAdd(base + 3, v.w);
    if (lane == 0) atomicAdd(&counts[g], 1.0f);
}

// ---------------- head ----------------
__global__ void head_kernel(const float* __restrict__ pooled, const float* __restrict__ counts,
                            const float* __restrict__ W1, const float* __restrict__ b1,
                            const float* __restrict__ W2, const float* __restrict__ b2,
                            float* __restrict__ out) {
    int g = blockIdx.x;
    int t = threadIdx.x;
    __shared__ float p[128];
    __shared__ float h1[128];
    __shared__ float logits[N_OUT];

    float cnt = fmaxf(counts[g], 1.0f);
    p[t] = pooled[g * 128 + t] / cnt;
    __syncthreads();

    float acc = b1[t];
#pragma unroll 8
    for (int k = 0; k < 128; k++) acc += p[k] * W1[k * 128 + t];
    h1[t] = fmaxf(acc, 0.0f);
    __syncthreads();

    if (t < N_OUT) {
        float a = b2[t];
#pragma unroll 8
        for (int k = 0; k < 128; k++) a += h1[k] * W2[k * N_OUT + t];
        logits[t] = a;
    }
    __syncthreads();

    if (t == 0) {
        float m = -1e30f;
#pragma unroll
        for (int o = 0; o < N_OUT; o++) m = fmaxf(m, logits[o]);
        float e[N_OUT], s = 0.0f;
#pragma unroll
        for (int o = 0; o < N_OUT; o++) { e[o] = __expf(logits[o] - m); s += e[o]; }
        float inv = 1.0f / s;
#pragma unroll
        for (int o = 0; o < N_OUT; o++) out[g * N_OUT + o] = e[o] * inv;
    }
}

// ---------------- launch ----------------
extern "C" void kernel_launch(void* const* d_in, const int* in_sizes, int n_in,
                              void* d_out, int out_size) {
    const float* x        = (const float*)d_in[0];
    const int*   edge_src = (const int*)  d_in[1];
    const int*   edge_dst = (const int*)  d_in[2];
    const int*   graph_id = (const int*)  d_in[3];
    const float* conv_W   = (const float*)d_in[4];
    const float* conv_b   = (const float*)d_in[5];
    const float* d1_W     = (const float*)d_in[6];
    const float* d1_b     = (const float*)d_in[7];
    const float* d2_W     = (const float*)d_in[8];
    const float* d2_b     = (const float*)d_in[9];
    float* out = (float*)d_out;

    float *z, *t1, *t2, *h, *pooled, *counts;
    __half* Wh;
    int *deg, *cursor, *rowptr, *csrsrc, *bsums;
    cudaGetSymbolAddress((void**)&z,      g_z);
    cudaGetSymbolAddress((void**)&t1,     g_t1);
    cudaGetSymbolAddress((void**)&t2,     g_t2);
    cudaGetSymbolAddress((void**)&h,      g_h);
    cudaGetSymbolAddress((void**)&Wh,     g_Wh);
    cudaGetSymbolAddress((void**)&pooled, g_pooled);
    cudaGetSymbolAddress((void**)&counts, g_counts);
    cudaGetSymbolAddress((void**)&deg,    g_deg);
    cudaGetSymbolAddress((void**)&cursor, g_cursor);
    cudaGetSymbolAddress((void**)&rowptr, g_rowptr);
    cudaGetSymbolAddress((void**)&csrsrc, g_csrsrc);
    cudaGetSymbolAddress((void**)&bsums,  g_bsums);

    cudaFuncSetAttribute(gemm_fp16, cudaFuncAttributeMaxDynamicSharedMemorySize, GEMM_SMEM);

    const int TB = 256;
    const int scanBlocks = (N_NODES + 1023) / 1024;  // 49

    // ---- weight prep (independent) + CSR build ----
    wh_prep<<<dim3(4, 4, 9), dim3(32, 8)>>>(conv_W, Wh);
    zero_deg_cursor<<<(N_NODES + TB - 1) / TB, TB>>>(deg, cursor);
    count_deg<<<(N_EDGES + TB - 1) / TB, TB>>>(edge_dst, deg);
    scan_blocks<<<scanBlocks, 1024>>>(deg, rowptr, bsums);
    add_boff<<<scanBlocks, 1024>>>(rowptr, bsums, scanBlocks);
    scatter_edges<<<(N_EDGES + TB - 1) / TB, TB>>>(edge_src, edge_dst, rowptr, cursor, csrsrc);

    const int aggBlocks  = (N_NODES * 32 + TB - 1) / TB;
    const int gemmBlocks = (N_NODES + 127) / 128;   // 391

    const float* hin = x;
    for (int l = 0; l < 3; l++) {
        const __half* Wh0 = Wh + (size_t)(l * 3 + 0) * CH * CH;
        const __half* Wh1 = Wh + (size_t)(l * 3 + 1) * CH * CH;
        const __half* Wh2 = Wh + (size_t)(l * 3 + 2) * CH * CH;
        const float* b0  = conv_b + (size_t)(l * 3 + 0) * CH;
        const float* b1p = conv_b + (size_t)(l * 3 + 1) * CH;
        const float* b2p = conv_b + (size_t)(l * 3 + 2) * CH;

        agg_kernel<<<aggBlocks, TB>>>(hin, z, rowptr, csrsrc);
        gemm_fp16<<<gemmBlocks, 256, GEMM_SMEM>>>(z,  Wh0, b0,  t1, N_NODES, 1);
        gemm_fp16<<<gemmBlocks, 256, GEMM_SMEM>>>(t1, Wh1, b1p, t2, N_NODES, 1);
        gemm_fp16<<<gemmBlocks, 256, GEMM_SMEM>>>(t2, Wh2, b2p, h,  N_NODES, 0);
        hin = h;
    }

    zero_pool<<<(N_GRAPHS * CH + TB - 1) / TB, TB>>>(pooled, counts);
    pool_kernel<<<aggBlocks, TB>>>(h, graph_id, pooled, counts);
    head_kernel<<<N_GRAPHS, 128>>>(pooled, counts, d1_W, d1_b, d2_W, d2_b, out);
}